// round 6
// baseline (speedup 1.0000x reference)
#include <cuda_runtime.h>
#include <string.h>

#define NN 50000
#define NE 800000
#define H  128
#define NG 512

// ---------------- scratch (static device globals; no allocation) ----------------
__device__ int   g_degi[NN];
__device__ float g_deginv[NN];
__device__ int   g_rowptr[NN + 1];
__device__ int   g_cursor[NN];
__device__ int   g_esrc[NE];                      // CSR: source node per in-edge
__device__ float g_xa[(size_t)NN * H];
__device__ float g_xb[(size_t)NN * H];
__device__ float g_pool[NG * H];

// ---------------- helpers ----------------
__device__ __forceinline__ void red4(float* p, float4 v) {
    asm volatile("red.global.add.v4.f32 [%0], {%1, %2, %3, %4};"
                 :: "l"(p), "f"(v.x), "f"(v.y), "f"(v.z), "f"(v.w) : "memory");
}

__device__ __forceinline__ unsigned long long dup2(float a) {
    unsigned long long r;
    asm("mov.b64 %0, {%1, %1};" : "=l"(r) : "f"(a));
    return r;
}

__device__ __forceinline__ unsigned long long fma2(unsigned long long a,
                                                   unsigned long long b,
                                                   unsigned long long c) {
    unsigned long long d;
    asm("fma.rn.f32x2 %0, %1, %2, %3;" : "=l"(d) : "l"(a), "l"(b), "l"(c));
    return d;
}

__device__ __forceinline__ float4 f4add(float4 a, float4 b) {
    return make_float4(a.x + b.x, a.y + b.y, a.z + b.z, a.w + b.w);
}

// ---------------- kernels ----------------

__global__ void init_kernel() {
    int i = blockIdx.x * blockDim.x + threadIdx.x;
    if (i < NN) g_degi[i] = 0;
    if (i < NG * H) g_pool[i] = 0.0f;   // NG*H = 65536 >= NN
}

__global__ void deg_kernel(const int* __restrict__ dst) {
    int e = blockIdx.x * blockDim.x + threadIdx.x;
    if (e < NE) atomicAdd(&g_degi[dst[e]], 1);
}

// single-block exclusive scan over g_degi -> g_rowptr / g_cursor, plus deg_inv
#define SCAN_T 1024
__global__ void scan_kernel() {
    __shared__ int sm[SCAN_T];
    int t = threadIdx.x;
    const int C = (NN + SCAN_T - 1) / SCAN_T;   // 49
    int b = t * C;
    int e = b + C; if (e > NN) e = NN;
    if (b > NN) b = NN;
    int s = 0;
    for (int i = b; i < e; i++) s += g_degi[i];
    sm[t] = s;
    __syncthreads();
    for (int off = 1; off < SCAN_T; off <<= 1) {
        int v = (t >= off) ? sm[t - off] : 0;
        __syncthreads();
        sm[t] += v;
        __syncthreads();
    }
    int base = (t > 0) ? sm[t - 1] : 0;   // exclusive prefix
    for (int i = b; i < e; i++) {
        g_rowptr[i] = base;
        g_cursor[i] = base;
        int d = g_degi[i];
        g_deginv[i] = 1.0f / fmaxf((float)d, 1.0f);
        base += d;
    }
    if (t == SCAN_T - 1) g_rowptr[NN] = base;
}

__global__ void fill_kernel(const int* __restrict__ src, const int* __restrict__ dst) {
    int e = blockIdx.x * blockDim.x + threadIdx.x;
    if (e < NE) {
        int p = atomicAdd(&g_cursor[dst[e]], 1);
        g_esrc[p] = src[e];
    }
}

// x = z_emb[z]  (one warp per node, float4 per lane)
__global__ void embed_kernel(const int* __restrict__ z, const float* __restrict__ z_emb) {
    int idx = blockIdx.x * blockDim.x + threadIdx.x;
    if (idx >= NN * 32) return;
    int node = idx >> 5, lane = idx & 31;
    float4 v = *reinterpret_cast<const float4*>(z_emb + (size_t)z[node] * H + lane * 4);
    *reinterpret_cast<float4*>(g_xa + (size_t)node * H + lane * 4) = v;
}

// Fused: As = deg_inv * csr_gather_sum(x), then out = act(As @ Wl + bl + Xs @ Wr)
// 64 rows x 128 cols per block, 256 threads (8 warps x 8 rows), f32x2 packed FMA,
// gather 4-way unrolled for MLP, GEMM k in pairs via LDS.64, k-loop unroll 2.
template <bool RELU>
__global__ void __launch_bounds__(256)
sage_layer_kernel(const float* __restrict__ x,
                  const float* __restrict__ Wl,
                  const float* __restrict__ bl,
                  const float* __restrict__ Wr,
                  float* __restrict__ out) {
    extern __shared__ float smf[];
    float* As = smf;            // 64 x 128
    float* Xs = smf + 64 * H;   // 64 x 128

    int row0 = blockIdx.x * 64;
    int tid = threadIdx.x;
    int lane = tid & 31;
    int w = tid >> 5;

    // stage Xs (tile's own rows)
    for (int i = tid; i < 64 * (H / 4); i += 256) {
        int r = i >> 5;
        int c4 = (i & 31) * 4;
        int row = row0 + r;
        float4 xv = make_float4(0, 0, 0, 0);
        if (row < NN)
            xv = *reinterpret_cast<const float4*>(x + (size_t)row * H + c4);
        *reinterpret_cast<float4*>(Xs + r * H + c4) = xv;
    }

    // gather As: warp w owns rows w*8 .. w*8+7; 4 independent accumulators (MLP=4)
    #pragma unroll 1
    for (int i = 0; i < 8; i++) {
        int r = w * 8 + i;
        int row = row0 + r;
        float4 a0 = make_float4(0, 0, 0, 0);
        float4 a1 = a0, a2 = a0, a3 = a0;
        if (row < NN) {
            int beg = g_rowptr[row];
            int end = g_rowptr[row + 1];
            int e = beg;
            for (; e + 4 <= end; e += 4) {
                int s0 = g_esrc[e];
                int s1 = g_esrc[e + 1];
                int s2 = g_esrc[e + 2];
                int s3 = g_esrc[e + 3];
                float4 v0 = *reinterpret_cast<const float4*>(x + (size_t)s0 * H + lane * 4);
                float4 v1 = *reinterpret_cast<const float4*>(x + (size_t)s1 * H + lane * 4);
                float4 v2 = *reinterpret_cast<const float4*>(x + (size_t)s2 * H + lane * 4);
                float4 v3 = *reinterpret_cast<const float4*>(x + (size_t)s3 * H + lane * 4);
                a0 = f4add(a0, v0);
                a1 = f4add(a1, v1);
                a2 = f4add(a2, v2);
                a3 = f4add(a3, v3);
            }
            for (; e < end; e++) {
                int s0 = g_esrc[e];
                a0 = f4add(a0, *reinterpret_cast<const float4*>(x + (size_t)s0 * H + lane * 4));
            }
            float di = g_deginv[row];
            a0 = f4add(f4add(a0, a1), f4add(a2, a3));
            a0.x *= di; a0.y *= di; a0.z *= di; a0.w *= di;
        }
        *reinterpret_cast<float4*>(As + r * H + lane * 4) = a0;
    }
    __syncthreads();

    int col = lane * 4;   // this thread's 4 output columns
    int r0 = w * 8;       // this thread's 8 rows

    ulonglong2 acc[8];
    {
        ulonglong2 bv = *reinterpret_cast<const ulonglong2*>(bl + col);
        #pragma unroll
        for (int i = 0; i < 8; i++) acc[i] = bv;
    }

    // mainloop: k in pairs, LDS.64 along the contiguous k-dim of As/Xs;
    // unroll 2 so ptxas front-batches the next step's weight LDGs.
    #pragma unroll 2
    for (int k = 0; k < H; k += 2) {
        ulonglong2 wl0 = *reinterpret_cast<const ulonglong2*>(Wl + (k + 0) * H + col);
        ulonglong2 wl1 = *reinterpret_cast<const ulonglong2*>(Wl + (k + 1) * H + col);
        ulonglong2 wr0 = *reinterpret_cast<const ulonglong2*>(Wr + (k + 0) * H + col);
        ulonglong2 wr1 = *reinterpret_cast<const ulonglong2*>(Wr + (k + 1) * H + col);
        #pragma unroll
        for (int i = 0; i < 8; i++) {
            float2 a  = *reinterpret_cast<const float2*>(As + (r0 + i) * H + k);
            float2 xv = *reinterpret_cast<const float2*>(Xs + (r0 + i) * H + k);
            unsigned long long a20 = dup2(a.x),  a21 = dup2(a.y);
            unsigned long long x20 = dup2(xv.x), x21 = dup2(xv.y);
            acc[i].x = fma2(a20, wl0.x, acc[i].x);
            acc[i].y = fma2(a20, wl0.y, acc[i].y);
            acc[i].x = fma2(x20, wr0.x, acc[i].x);
            acc[i].y = fma2(x20, wr0.y, acc[i].y);
            acc[i].x = fma2(a21, wl1.x, acc[i].x);
            acc[i].y = fma2(a21, wl1.y, acc[i].y);
            acc[i].x = fma2(x21, wr1.x, acc[i].x);
            acc[i].y = fma2(x21, wr1.y, acc[i].y);
        }
    }

    #pragma unroll
    for (int i = 0; i < 8; i++) {
        int row = row0 + r0 + i;
        if (row < NN) {
            float4 v;
            memcpy(&v, &acc[i], 16);
            if (RELU) {
                v.x = fmaxf(v.x, 0.0f); v.y = fmaxf(v.y, 0.0f);
                v.z = fmaxf(v.z, 0.0f); v.w = fmaxf(v.w, 0.0f);
            }
            *reinterpret_cast<float4*>(out + (size_t)row * H + col) = v;
        }
    }
}

// segmented pool over sorted batch: one warp handles 64 consecutive nodes,
// accumulates in registers, flushes on batch change (few atomics total).
#define POOL_CHUNK 64
__global__ void pool_kernel(const float* __restrict__ x, const int* __restrict__ batch) {
    int wid = (blockIdx.x * blockDim.x + threadIdx.x) >> 5;
    int lane = threadIdx.x & 31;
    int n0 = wid * POOL_CHUNK;
    if (n0 >= NN) return;
    int end = n0 + POOL_CHUNK;
    if (end > NN) end = NN;

    float4 acc = make_float4(0, 0, 0, 0);
    int cur = batch[n0];
    for (int n = n0; n < end; n++) {
        int b = batch[n];
        if (b != cur) {
            red4(g_pool + (size_t)cur * H + lane * 4, acc);
            acc = make_float4(0, 0, 0, 0);
            cur = b;
        }
        float4 v = *reinterpret_cast<const float4*>(x + (size_t)n * H + lane * 4);
        acc = f4add(acc, v);
    }
    red4(g_pool + (size_t)cur * H + lane * 4, acc);
}

// per-graph MLP: h = relu(g @ W1 + b1); out = h @ W2 + b2
__global__ void mlp_kernel(const float* __restrict__ W1, const float* __restrict__ b1,
                           const float* __restrict__ W2, const float* __restrict__ b2,
                           float* __restrict__ out) {
    __shared__ float gs[H];
    __shared__ float redv[4];
    int gid = blockIdx.x;
    int j = threadIdx.x;
    gs[j] = g_pool[(size_t)gid * H + j];
    __syncthreads();

    float acc = b1[j];
    #pragma unroll 4
    for (int k = 0; k < H; k++) acc += gs[k] * W1[k * H + j];
    float hv = fmaxf(acc, 0.0f) * W2[j];

    #pragma unroll
    for (int o = 16; o > 0; o >>= 1) hv += __shfl_down_sync(0xFFFFFFFFu, hv, o);
    if ((j & 31) == 0) redv[j >> 5] = hv;
    __syncthreads();
    if (j == 0) out[gid] = redv[0] + redv[1] + redv[2] + redv[3] + b2[0];
}

// ---------------- launch ----------------
extern "C" void kernel_launch(void* const* d_in, const int* in_sizes, int n_in,
                              void* d_out, int out_size) {
    const int*   z     = (const int*)d_in[0];
    const int*   ei    = (const int*)d_in[1];
    const int*   batch = (const int*)d_in[2];
    const float* z_emb = (const float*)d_in[3];
    const float* Wl0 = (const float*)d_in[4];
    const float* bl0 = (const float*)d_in[5];
    const float* Wr0 = (const float*)d_in[6];
    const float* Wl1 = (const float*)d_in[7];
    const float* bl1 = (const float*)d_in[8];
    const float* Wr1 = (const float*)d_in[9];
    const float* Wl2 = (const float*)d_in[10];
    const float* bl2 = (const float*)d_in[11];
    const float* Wr2 = (const float*)d_in[12];
    const float* W1  = (const float*)d_in[13];
    const float* b1  = (const float*)d_in[14];
    const float* W2  = (const float*)d_in[15];
    const float* b2  = (const float*)d_in[16];
    const int* src = ei;
    const int* dst = ei + NE;
    float* out = (float*)d_out;

    void *pxa_, *pxb_;
    cudaGetSymbolAddress(&pxa_, g_xa);
    cudaGetSymbolAddress(&pxb_, g_xb);
    float* xa = (float*)pxa_;
    float* xb = (float*)pxb_;

    const int SMEM = 64 * H * 2 * sizeof(float);  // 65536
    cudaFuncSetAttribute((const void*)sage_layer_kernel<true>,
                         cudaFuncAttributeMaxDynamicSharedMemorySize, SMEM);
    cudaFuncSetAttribute((const void*)sage_layer_kernel<false>,
                         cudaFuncAttributeMaxDynamicSharedMemorySize, SMEM);

    const int gemm_blocks = (NN + 63) / 64;              // 782
    const int pool_warps  = (NN + POOL_CHUNK - 1) / POOL_CHUNK;
    const int pool_blocks = (pool_warps + 7) / 8;        // 8 warps/block

    // degree + CSR build (shared by all 3 layers)
    init_kernel<<<(NG * H + 255) / 256, 256>>>();
    deg_kernel<<<(NE + 255) / 256, 256>>>(dst);
    scan_kernel<<<1, SCAN_T>>>();
    fill_kernel<<<(NE + 255) / 256, 256>>>(src, dst);
    embed_kernel<<<(NN * 32 + 255) / 256, 256>>>(z, z_emb);

    // layers (gather fused into GEMM staging)
    sage_layer_kernel<true ><<<gemm_blocks, 256, SMEM>>>(xa, Wl0, bl0, Wr0, xb);
    sage_layer_kernel<true ><<<gemm_blocks, 256, SMEM>>>(xb, Wl1, bl1, Wr1, xa);
    sage_layer_kernel<false><<<gemm_blocks, 256, SMEM>>>(xa, Wl2, bl2, Wr2, xb);

    // pool + MLP head
    pool_kernel<<<pool_blocks, 256>>>(xb, batch);
    mlp_kernel<<<NG, H>>>(W1, b1, W2, b2, out);
}